// round 15
// baseline (speedup 1.0000x reference)
#include <cuda_runtime.h>
#include <cuda_fp16.h>
#include <cstdint>

// Best structure (round 14) + occupancy/L1 tuning.
// 1) prep    : merged convert_w + prep_s (block-range split)
// 2) gemm1f  : fused resid+LN-fold GEMM1, occ 3
// 3) gemm2   : no ssc staging; epilogue reads shortcut via __ldg from g_sc

#define NTOK 32768
#define DDIM 1024
#define BN   128

__device__ __align__(16) __half g_sc[(size_t)NTOK * DDIM];   // 64MB
__device__ __align__(16) __half g_hd[(size_t)NTOK * BN];     // 8MB
__device__ __align__(16) __half g_Wd[BN * DDIM];
__device__ __align__(16) __half g_Wu[DDIM * BN];
__device__ float g_s1[BN];
__device__ float g_s2[BN];

__device__ __forceinline__ void mma16(float* c, const uint32_t* a, const uint32_t* b) {
    asm volatile(
        "mma.sync.aligned.m16n8k16.row.col.f32.f16.f16.f32 "
        "{%0,%1,%2,%3}, {%4,%5,%6,%7}, {%8,%9}, {%0,%1,%2,%3};\n"
        : "+f"(c[0]), "+f"(c[1]), "+f"(c[2]), "+f"(c[3])
        : "r"(a[0]), "r"(a[1]), "r"(a[2]), "r"(a[3]), "r"(b[0]), "r"(b[1]));
}

__device__ __forceinline__ void ldsm4(uint32_t* r, const __half* p) {
    uint32_t a = (uint32_t)__cvta_generic_to_shared(p);
    asm volatile("ldmatrix.sync.aligned.m8n8.x4.shared.b16 {%0,%1,%2,%3}, [%4];\n"
                 : "=r"(r[0]), "=r"(r[1]), "=r"(r[2]), "=r"(r[3]) : "r"(a));
}

__device__ __forceinline__ void cp16(void* dst_sm, const void* src) {
    uint32_t a = (uint32_t)__cvta_generic_to_shared(dst_sm);
    asm volatile("cp.async.cg.shared.global [%0], [%1], 16;\n" :: "r"(a), "l"(src));
}
__device__ __forceinline__ void cp_commit() {
    asm volatile("cp.async.commit_group;\n");
}
template <int N>
__device__ __forceinline__ void cp_wait() {
    asm volatile("cp.async.wait_group %0;\n" :: "n"(N));
}

// ------------------------------------------------------------------ kernel 1
// blocks 0..127: weight convert; blocks 128..255: s1/s2 reduction
__global__ __launch_bounds__(256) void prep(
    const float* __restrict__ Wd, const float* __restrict__ Wu,
    const float* __restrict__ gamma, const float* __restrict__ beta,
    const float* __restrict__ bd)
{
    if (blockIdx.x < 128) {
        const int i = (blockIdx.x * 256 + threadIdx.x) * 4;
        float4 a = *(const float4*)(Wd + i);
        const int k = i & 1023;
        const float4 g = *(const float4*)(gamma + k);
        a.x *= g.x; a.y *= g.y; a.z *= g.z; a.w *= g.w;
        const float4 b = *(const float4*)(Wu + i);
        __half2 a0 = __floats2half2_rn(a.x, a.y), a1 = __floats2half2_rn(a.z, a.w);
        __half2 b0 = __floats2half2_rn(b.x, b.y), b1 = __floats2half2_rn(b.z, b.w);
        uint2 ua, ub;
        ua.x = *(uint32_t*)&a0; ua.y = *(uint32_t*)&a1;
        ub.x = *(uint32_t*)&b0; ub.y = *(uint32_t*)&b1;
        *(uint2*)(g_Wd + i) = ua;
        *(uint2*)(g_Wu + i) = ub;
    } else {
        __shared__ float r1[256], r2[256];
        const int j = blockIdx.x - 128;
        const int tid = threadIdx.x;
        const float* wr = Wd + (size_t)j * DDIM;
        float s1 = 0.f, s2 = 0.f;
        for (int k = tid; k < DDIM; k += 256) {
            const float w = wr[k];
            s1 += gamma[k] * w;
            s2 += beta[k] * w;
        }
        r1[tid] = s1; r2[tid] = s2;
        __syncthreads();
        for (int o = 128; o > 0; o >>= 1) {
            if (tid < o) { r1[tid] += r1[tid + o]; r2[tid] += r2[tid + o]; }
            __syncthreads();
        }
        if (tid == 0) { g_s1[j] = r1[0]; g_s2[j] = r2[0] + bd[j]; }
    }
}

// ------------------------------------------------------------------ kernel 2
// gemm1f: CTA = 64 tokens x 128(BN), 256 threads (8 warps = 2m x 4n), occ 3.
static constexpr int F_S1   = 0;                         // 128 f
static constexpr int F_S2   = 512;
static constexpr int F_RED  = 1024;                      // 64*4*2 f = 2048B
static constexpr int F_MU   = 3072;                      // 64 f
static constexpr int F_RS   = 3328;                      // 64 f
static constexpr int F_V    = 3584;                      // 2 x 64*72 halves
static constexpr int V_STG  = 64 * 72;
static constexpr int F_WD   = F_V + 2 * V_STG * 2;       // 2 x 128*72 halves
static constexpr int WD_STG = 128 * 72;
static constexpr int F_SMEM = F_WD + 2 * WD_STG * 2;     // 58112 B

__global__ __launch_bounds__(256, 3) void gemm1f(
    const float* __restrict__ x, const float* __restrict__ res)
{
    extern __shared__ char smem1[];
    float*  ss1  = (float*)(smem1 + F_S1);
    float*  ss2  = (float*)(smem1 + F_S2);
    float*  sred = (float*)(smem1 + F_RED);
    float*  smu  = (float*)(smem1 + F_MU);
    float*  srs  = (float*)(smem1 + F_RS);
    __half* smV  = (__half*)(smem1 + F_V);
    __half* smWd = (__half*)(smem1 + F_WD);

    const int tid  = threadIdx.x;
    const int lane = tid & 31, warp = tid >> 5;
    const int t0   = blockIdx.x * 64;

    const int mw = warp >> 2, nw = warp & 3;      // 2 x 4
    const int gid = lane >> 2, tig = lane & 3;
    const int a_row = (lane & 7) + ((lane >> 3) & 1) * 8;
    const int a_kof = (lane >> 4) * 8;
    const int b_row = (lane & 7) + (lane >> 4) * 8;
    const int b_kof = ((lane >> 3) & 1) * 8;

    if (tid < 128) { ss1[tid] = g_s1[tid]; ss2[tid] = g_s2[tid]; }

    const int prow = tid >> 2;
    const int pc0  = (tid & 3) * 16;
    const int n    = t0 + prow;
    const int ps   = n >> 3, pb = n & 7;
    const float* xrow = x + (size_t)n * DDIM;
    const float* rrow = res + ((size_t)pb * 4096 + ps) * DDIM;

    auto issueWd = [&](int st, int kc) {
        __half* s = smWd + st * WD_STG;
        const int kg0 = kc * 64;
        #pragma unroll
        for (int p = 0; p < 4; ++p) {
            const int idx = p * 256 + tid;
            const int nn = idx >> 3, j = (idx & 7) * 8;
            cp16(s + nn * 72 + j, g_Wd + (size_t)nn * DDIM + kg0 + j);
        }
        cp_commit();
    };

    float4 rx[4], rr[4];
    auto loadregs = [&](int kc) {
        const int o = kc * 64 + pc0;
        #pragma unroll
        for (int i = 0; i < 4; ++i) {
            rx[i] = *(const float4*)(xrow + o + i * 4);
            rr[i] = *(const float4*)(rrow + o + i * 4);
        }
    };

    float psum = 0.f, psq = 0.f;
    auto produce = [&](int kc) {
        uint32_t o[4];
        #pragma unroll
        for (int i = 0; i < 2; ++i) {
            float4 t0v, t1v;
            t0v.x = rx[2*i].x + rr[2*i].x;   t0v.y = rx[2*i].y + rr[2*i].y;
            t0v.z = rx[2*i].z + rr[2*i].z;   t0v.w = rx[2*i].w + rr[2*i].w;
            t1v.x = rx[2*i+1].x + rr[2*i+1].x; t1v.y = rx[2*i+1].y + rr[2*i+1].y;
            t1v.z = rx[2*i+1].z + rr[2*i+1].z; t1v.w = rx[2*i+1].w + rr[2*i+1].w;
            psum += t0v.x + t0v.y + t0v.z + t0v.w + t1v.x + t1v.y + t1v.z + t1v.w;
            psq  += t0v.x*t0v.x + t0v.y*t0v.y + t0v.z*t0v.z + t0v.w*t0v.w
                  + t1v.x*t1v.x + t1v.y*t1v.y + t1v.z*t1v.z + t1v.w*t1v.w;
            __half2 h0 = __floats2half2_rn(t0v.x, t0v.y);
            __half2 h1 = __floats2half2_rn(t0v.z, t0v.w);
            __half2 h2 = __floats2half2_rn(t1v.x, t1v.y);
            __half2 h3 = __floats2half2_rn(t1v.z, t1v.w);
            o[0] = *(uint32_t*)&h0; o[1] = *(uint32_t*)&h1;
            o[2] = *(uint32_t*)&h2; o[3] = *(uint32_t*)&h3;
            __half* vs = smV + (kc & 1) * V_STG + prow * 72 + pc0 + i * 8;
            *(uint4*)vs = *(uint4*)o;
            *(uint4*)(g_sc + (size_t)n * DDIM + kc * 64 + pc0 + i * 8) = *(uint4*)o;
        }
    };

    issueWd(0, 0);
    issueWd(1, 1);
    loadregs(0);
    produce(0);

    float acc[2][4][4];
    #pragma unroll
    for (int i = 0; i < 2; ++i)
        #pragma unroll
        for (int j = 0; j < 4; ++j)
            #pragma unroll
            for (int q = 0; q < 4; ++q) acc[i][j][q] = 0.f;

    #pragma unroll 1
    for (int kc = 0; kc < 16; ++kc) {
        if (kc + 1 < 16) loadregs(kc + 1);
        if (kc == 15) cp_wait<0>(); else cp_wait<1>();
        __syncthreads();
        const __half* sa = smV + (kc & 1) * V_STG;
        const __half* sb = smWd + (kc & 1) * WD_STG;
        #pragma unroll
        for (int ks = 0; ks < 4; ++ks) {
            const int kb0 = ks * 16;
            uint32_t a[2][4], bf[2][4];
            #pragma unroll
            for (int mt = 0; mt < 2; ++mt)
                ldsm4(a[mt], sa + (mw * 32 + mt * 16 + a_row) * 72 + kb0 + a_kof);
            #pragma unroll
            for (int nt2 = 0; nt2 < 2; ++nt2)
                ldsm4(bf[nt2], sb + (nw * 32 + nt2 * 16 + b_row) * 72 + kb0 + b_kof);
            #pragma unroll
            for (int mt = 0; mt < 2; ++mt)
                #pragma unroll
                for (int nt = 0; nt < 4; ++nt)
                    mma16(acc[mt][nt], a[mt], bf[nt >> 1] + (nt & 1) * 2);
        }
        __syncthreads();
        if (kc + 2 < 16) issueWd(kc & 1, kc + 2);
        if (kc + 1 < 16) produce(kc + 1);
    }

    // LN stats reduction
    sred[prow * 8 + (tid & 3) * 2]     = psum;
    sred[prow * 8 + (tid & 3) * 2 + 1] = psq;
    __syncthreads();
    if (tid < 64) {
        float s = 0.f, q = 0.f;
        #pragma unroll
        for (int i = 0; i < 4; ++i) {
            s += sred[tid * 8 + i * 2];
            q += sred[tid * 8 + i * 2 + 1];
        }
        const float mu  = s * (1.f / 1024.f);
        const float var = q * (1.f / 1024.f) - mu * mu;
        smu[tid] = mu;
        srs[tid] = rsqrtf(var + 1e-5f);
    }
    __syncthreads();

    // epilogue: hd = relu(rstd*(acc - mu*s1) + s2) -> g_hd
    #pragma unroll
    for (int mt = 0; mt < 2; ++mt) {
        #pragma unroll
        for (int nt = 0; nt < 4; ++nt) {
            const int row = mw * 32 + mt * 16 + gid;
            const int col = nw * 32 + nt * 8 + 2 * tig;
            const float mu0 = smu[row],     rs0 = srs[row];
            const float mu1 = smu[row + 8], rs1 = srs[row + 8];
            const float s10 = ss1[col], s11 = ss1[col + 1];
            const float s20 = ss2[col], s21 = ss2[col + 1];
            const float* c = acc[mt][nt];
            const size_t o = (size_t)(t0 + row) * BN + col;
            __half2 h0 = __floats2half2_rn(
                fmaxf(rs0 * (c[0] - mu0 * s10) + s20, 0.f),
                fmaxf(rs0 * (c[1] - mu0 * s11) + s21, 0.f));
            __half2 h1 = __floats2half2_rn(
                fmaxf(rs1 * (c[2] - mu1 * s10) + s20, 0.f),
                fmaxf(rs1 * (c[3] - mu1 * s11) + s21, 0.f));
            *(uint32_t*)(g_hd + o)          = *(uint32_t*)&h0;
            *(uint32_t*)(g_hd + o + 8 * BN) = *(uint32_t*)&h1;
        }
    }
}

// ------------------------------------------------------------------ kernel 3
// CTA: 128 tokens x 128 out-cols, 512 threads (16 warps 4x4). Grid (8, 256).
// NO ssc staging: epilogue reads shortcut directly from g_sc (__ldg, L2-hot).
static constexpr int G2_ST    = 136;                   // halves
static constexpr int G2_HD    = 0;                     // shd 128x136
static constexpr int G2_WU    = 128 * G2_ST;           // swu 128x136
static constexpr int G2_END   = G2_WU + 128 * G2_ST;   // halves
static constexpr int G2_SMEM  = G2_END * 2 + 128 * 4;  // 70144 B

__global__ __launch_bounds__(512, 2) void gemm2(
    const float* __restrict__ bup, float* __restrict__ out)
{
    extern __shared__ __half smC[];
    __half* shd = smC + G2_HD;
    __half* swu = smC + G2_WU;
    float*  sbup = (float*)(smC + G2_END);
    const int tid  = threadIdx.x;
    const int lane = tid & 31, warp = tid >> 5;
    const int nc = blockIdx.x;                 // col chunk (fastest)
    const int t0 = blockIdx.y * 128;           // token tile

    const int mw = warp >> 2, nw = warp & 3;   // 4 x 4
    const int gid = lane >> 2, tig = lane & 3;

    const int a_row = (lane & 7) + ((lane >> 3) & 1) * 8;
    const int a_kof = (lane >> 4) * 8;
    const int b_row = (lane & 7) + (lane >> 4) * 8;
    const int b_kof = ((lane >> 3) & 1) * 8;

    #pragma unroll
    for (int hk = 0; hk < 2; ++hk) {
        const int k0 = hk * 64;
        #pragma unroll
        for (int p = 0; p < 2; ++p) {           // hd: 128 x 64 halves
            const int idx = p * 512 + tid;
            const int row = idx >> 3, j = (idx & 7) * 8;
            cp16(shd + row * G2_ST + k0 + j, g_hd + (size_t)(t0 + row) * BN + k0 + j);
        }
        #pragma unroll
        for (int p = 0; p < 2; ++p) {           // Wu: 128 x 64 halves
            const int idx = p * 512 + tid;
            const int nn = idx >> 3, j = (idx & 7) * 8;
            cp16(swu + nn * G2_ST + k0 + j,
                 g_Wu + (size_t)(nc * 128 + nn) * BN + k0 + j);
        }
        cp_commit();
    }
    if (tid < 32) cp16(sbup + tid * 4, bup + nc * 128 + tid * 4);
    cp_commit();

    float acc[2][4][4];
    #pragma unroll
    for (int i = 0; i < 2; ++i)
        #pragma unroll
        for (int j = 0; j < 4; ++j)
            #pragma unroll
            for (int q = 0; q < 4; ++q) acc[i][j][q] = 0.f;

    #pragma unroll
    for (int hk = 0; hk < 2; ++hk) {
        if (hk == 0) cp_wait<2>(); else cp_wait<1>();
        __syncthreads();
        #pragma unroll
        for (int ks = 0; ks < 4; ++ks) {
            const int kb0 = hk * 64 + ks * 16;
            uint32_t a[2][4], bf[2][4];
            #pragma unroll
            for (int mt = 0; mt < 2; ++mt)
                ldsm4(a[mt], shd + (mw * 32 + mt * 16 + a_row) * G2_ST + kb0 + a_kof);
            #pragma unroll
            for (int nt2 = 0; nt2 < 2; ++nt2)
                ldsm4(bf[nt2], swu + (nw * 32 + nt2 * 16 + b_row) * G2_ST + kb0 + b_kof);
            #pragma unroll
            for (int mt = 0; mt < 2; ++mt)
                #pragma unroll
                for (int nt = 0; nt < 4; ++nt)
                    mma16(acc[mt][nt], a[mt], bf[nt >> 1] + (nt & 1) * 2);
        }
    }

    cp_wait<0>();
    __syncthreads();

    #pragma unroll
    for (int mt = 0; mt < 2; ++mt) {
        #pragma unroll
        for (int nt = 0; nt < 4; ++nt) {
            const int row  = mw * 32 + mt * 16 + gid;
            const int col  = nw * 32 + nt * 8 + 2 * tig;
            const int gcol = nc * 128 + col;
            const float b0 = sbup[col], b1 = sbup[col + 1];
            const size_t off  = (size_t)(t0 + row) * DDIM + gcol;
            const size_t off2 = off + (size_t)8 * DDIM;
            const float* c = acc[mt][nt];
            const float2 s0 = __half22float2(__ldg((const __half2*)(g_sc + off)));
            const float2 s1 = __half22float2(__ldg((const __half2*)(g_sc + off2)));
            float2 o0, o1;
            o0.x = c[0] + b0 + s0.x; o0.y = c[1] + b1 + s0.y;
            o1.x = c[2] + b0 + s1.x; o1.y = c[3] + b1 + s1.y;
            *(float2*)(out + off)  = o0;
            *(float2*)(out + off2) = o1;
        }
    }
}

// ------------------------------------------------------------------ launch
extern "C" void kernel_launch(void* const* d_in, const int* in_sizes, int n_in,
                              void* d_out, int out_size) {
    const float* x     = (const float*)d_in[0];
    const float* res   = (const float*)d_in[1];
    const float* gamma = (const float*)d_in[2];
    const float* beta  = (const float*)d_in[3];
    const float* Wd    = (const float*)d_in[4];
    const float* bd    = (const float*)d_in[5];
    const float* Wu    = (const float*)d_in[6];
    const float* bup   = (const float*)d_in[7];
    float* out = (float*)d_out;

    static bool attr_done = false;
    if (!attr_done) {
        cudaFuncSetAttribute(gemm1f, cudaFuncAttributeMaxDynamicSharedMemorySize, F_SMEM);
        cudaFuncSetAttribute(gemm2, cudaFuncAttributeMaxDynamicSharedMemorySize, G2_SMEM);
        attr_done = true;
    }

    prep<<<256, 256>>>(Wd, Wu, gamma, beta, bd);
    gemm1f<<<512, 256, F_SMEM>>>(x, res);
    gemm2<<<dim3(8, 256), 512, G2_SMEM>>>(bup, out);
}

// round 16
// speedup vs baseline: 1.2785x; 1.2785x over previous
#include <cuda_runtime.h>
#include <cuda_fp16.h>
#include <cstdint>

// Round-14 proven kernels (best: 133.6us) + merged prep only.
// 1) prep   : convert_w + prep_s in one launch (block-range split)
// 2) gemm1f : fused resid+LN-fold GEMM1 (occ 2, register x/res prefetch)
// 3) gemm2  : TM=128 GEMM2 with cp.async ssc shortcut staging

#define NTOK 32768
#define DDIM 1024
#define BN   128

__device__ __align__(16) __half g_sc[(size_t)NTOK * DDIM];   // 64MB
__device__ __align__(16) __half g_hd[(size_t)NTOK * BN];     // 8MB
__device__ __align__(16) __half g_Wd[BN * DDIM];
__device__ __align__(16) __half g_Wu[DDIM * BN];
__device__ float g_s1[BN];
__device__ float g_s2[BN];

__device__ __forceinline__ void mma16(float* c, const uint32_t* a, const uint32_t* b) {
    asm volatile(
        "mma.sync.aligned.m16n8k16.row.col.f32.f16.f16.f32 "
        "{%0,%1,%2,%3}, {%4,%5,%6,%7}, {%8,%9}, {%0,%1,%2,%3};\n"
        : "+f"(c[0]), "+f"(c[1]), "+f"(c[2]), "+f"(c[3])
        : "r"(a[0]), "r"(a[1]), "r"(a[2]), "r"(a[3]), "r"(b[0]), "r"(b[1]));
}

__device__ __forceinline__ void ldsm4(uint32_t* r, const __half* p) {
    uint32_t a = (uint32_t)__cvta_generic_to_shared(p);
    asm volatile("ldmatrix.sync.aligned.m8n8.x4.shared.b16 {%0,%1,%2,%3}, [%4];\n"
                 : "=r"(r[0]), "=r"(r[1]), "=r"(r[2]), "=r"(r[3]) : "r"(a));
}

__device__ __forceinline__ void cp16(void* dst_sm, const void* src) {
    uint32_t a = (uint32_t)__cvta_generic_to_shared(dst_sm);
    asm volatile("cp.async.cg.shared.global [%0], [%1], 16;\n" :: "r"(a), "l"(src));
}
__device__ __forceinline__ void cp_commit() {
    asm volatile("cp.async.commit_group;\n");
}
template <int N>
__device__ __forceinline__ void cp_wait() {
    asm volatile("cp.async.wait_group %0;\n" :: "n"(N));
}

// ------------------------------------------------------------------ kernel 1
// blocks 0..127: weight convert; blocks 128..255: s1/s2 reduction
__global__ __launch_bounds__(256) void prep(
    const float* __restrict__ Wd, const float* __restrict__ Wu,
    const float* __restrict__ gamma, const float* __restrict__ beta,
    const float* __restrict__ bd)
{
    if (blockIdx.x < 128) {
        const int i = (blockIdx.x * 256 + threadIdx.x) * 4;
        float4 a = *(const float4*)(Wd + i);
        const int k = i & 1023;
        const float4 g = *(const float4*)(gamma + k);
        a.x *= g.x; a.y *= g.y; a.z *= g.z; a.w *= g.w;
        const float4 b = *(const float4*)(Wu + i);
        __half2 a0 = __floats2half2_rn(a.x, a.y), a1 = __floats2half2_rn(a.z, a.w);
        __half2 b0 = __floats2half2_rn(b.x, b.y), b1 = __floats2half2_rn(b.z, b.w);
        uint2 ua, ub;
        ua.x = *(uint32_t*)&a0; ua.y = *(uint32_t*)&a1;
        ub.x = *(uint32_t*)&b0; ub.y = *(uint32_t*)&b1;
        *(uint2*)(g_Wd + i) = ua;
        *(uint2*)(g_Wu + i) = ub;
    } else {
        __shared__ float r1[256], r2[256];
        const int j = blockIdx.x - 128;
        const int tid = threadIdx.x;
        const float* wr = Wd + (size_t)j * DDIM;
        float s1 = 0.f, s2 = 0.f;
        for (int k = tid; k < DDIM; k += 256) {
            const float w = wr[k];
            s1 += gamma[k] * w;
            s2 += beta[k] * w;
        }
        r1[tid] = s1; r2[tid] = s2;
        __syncthreads();
        for (int o = 128; o > 0; o >>= 1) {
            if (tid < o) { r1[tid] += r1[tid + o]; r2[tid] += r2[tid + o]; }
            __syncthreads();
        }
        if (tid == 0) { g_s1[j] = r1[0]; g_s2[j] = r2[0] + bd[j]; }
    }
}

// ------------------------------------------------------------------ kernel 2
// gemm1f: CTA = 64 tokens x 128(BN), 256 threads (8 warps = 2m x 4n), occ 2.
static constexpr int F_S1   = 0;                         // 128 f
static constexpr int F_S2   = 512;
static constexpr int F_RED  = 1024;                      // 64*4*2 f = 2048B
static constexpr int F_MU   = 3072;                      // 64 f
static constexpr int F_RS   = 3328;                      // 64 f
static constexpr int F_V    = 3584;                      // 2 x 64*72 halves
static constexpr int V_STG  = 64 * 72;
static constexpr int F_WD   = F_V + 2 * V_STG * 2;       // 2 x 128*72 halves
static constexpr int WD_STG = 128 * 72;
static constexpr int F_SMEM = F_WD + 2 * WD_STG * 2;     // 58112 B

__global__ __launch_bounds__(256, 2) void gemm1f(
    const float* __restrict__ x, const float* __restrict__ res)
{
    extern __shared__ char smem1[];
    float*  ss1  = (float*)(smem1 + F_S1);
    float*  ss2  = (float*)(smem1 + F_S2);
    float*  sred = (float*)(smem1 + F_RED);
    float*  smu  = (float*)(smem1 + F_MU);
    float*  srs  = (float*)(smem1 + F_RS);
    __half* smV  = (__half*)(smem1 + F_V);
    __half* smWd = (__half*)(smem1 + F_WD);

    const int tid  = threadIdx.x;
    const int lane = tid & 31, warp = tid >> 5;
    const int t0   = blockIdx.x * 64;

    const int mw = warp >> 2, nw = warp & 3;      // 2 x 4
    const int gid = lane >> 2, tig = lane & 3;
    const int a_row = (lane & 7) + ((lane >> 3) & 1) * 8;
    const int a_kof = (lane >> 4) * 8;
    const int b_row = (lane & 7) + (lane >> 4) * 8;
    const int b_kof = ((lane >> 3) & 1) * 8;

    if (tid < 128) { ss1[tid] = g_s1[tid]; ss2[tid] = g_s2[tid]; }

    // produce-thread mapping: each thread owns (row = tid>>2, 16 cols)
    const int prow = tid >> 2;
    const int pc0  = (tid & 3) * 16;
    const int n    = t0 + prow;
    const int ps   = n >> 3, pb = n & 7;
    const float* xrow = x + (size_t)n * DDIM;
    const float* rrow = res + ((size_t)pb * 4096 + ps) * DDIM;

    auto issueWd = [&](int st, int kc) {
        __half* s = smWd + st * WD_STG;
        const int kg0 = kc * 64;
        #pragma unroll
        for (int p = 0; p < 4; ++p) {
            const int idx = p * 256 + tid;
            const int nn = idx >> 3, j = (idx & 7) * 8;
            cp16(s + nn * 72 + j, g_Wd + (size_t)nn * DDIM + kg0 + j);
        }
        cp_commit();
    };

    float4 rx[4], rr[4];
    auto loadregs = [&](int kc) {
        const int o = kc * 64 + pc0;
        #pragma unroll
        for (int i = 0; i < 4; ++i) {
            rx[i] = *(const float4*)(xrow + o + i * 4);
            rr[i] = *(const float4*)(rrow + o + i * 4);
        }
    };

    float psum = 0.f, psq = 0.f;
    auto produce = [&](int kc) {                // consumes rx/rr
        uint32_t o[4];
        #pragma unroll
        for (int i = 0; i < 2; ++i) {
            float4 t0v, t1v;
            t0v.x = rx[2*i].x + rr[2*i].x;   t0v.y = rx[2*i].y + rr[2*i].y;
            t0v.z = rx[2*i].z + rr[2*i].z;   t0v.w = rx[2*i].w + rr[2*i].w;
            t1v.x = rx[2*i+1].x + rr[2*i+1].x; t1v.y = rx[2*i+1].y + rr[2*i+1].y;
            t1v.z = rx[2*i+1].z + rr[2*i+1].z; t1v.w = rx[2*i+1].w + rr[2*i+1].w;
            psum += t0v.x + t0v.y + t0v.z + t0v.w + t1v.x + t1v.y + t1v.z + t1v.w;
            psq  += t0v.x*t0v.x + t0v.y*t0v.y + t0v.z*t0v.z + t0v.w*t0v.w
                  + t1v.x*t1v.x + t1v.y*t1v.y + t1v.z*t1v.z + t1v.w*t1v.w;
            __half2 h0 = __floats2half2_rn(t0v.x, t0v.y);
            __half2 h1 = __floats2half2_rn(t0v.z, t0v.w);
            __half2 h2 = __floats2half2_rn(t1v.x, t1v.y);
            __half2 h3 = __floats2half2_rn(t1v.z, t1v.w);
            o[0] = *(uint32_t*)&h0; o[1] = *(uint32_t*)&h1;
            o[2] = *(uint32_t*)&h2; o[3] = *(uint32_t*)&h3;
            __half* vs = smV + (kc & 1) * V_STG + prow * 72 + pc0 + i * 8;
            *(uint4*)vs = *(uint4*)o;
            *(uint4*)(g_sc + (size_t)n * DDIM + kc * 64 + pc0 + i * 8) = *(uint4*)o;
        }
    };

    issueWd(0, 0);
    issueWd(1, 1);
    loadregs(0);
    produce(0);                                  // exposed once

    float acc[2][4][4];
    #pragma unroll
    for (int i = 0; i < 2; ++i)
        #pragma unroll
        for (int j = 0; j < 4; ++j)
            #pragma unroll
            for (int q = 0; q < 4; ++q) acc[i][j][q] = 0.f;

    #pragma unroll 1
    for (int kc = 0; kc < 16; ++kc) {
        if (kc + 1 < 16) loadregs(kc + 1);       // LDG overlaps MMA below
        if (kc == 15) cp_wait<0>(); else cp_wait<1>();
        __syncthreads();                          // v(kc), Wd(kc) visible
        const __half* sa = smV + (kc & 1) * V_STG;
        const __half* sb = smWd + (kc & 1) * WD_STG;
        #pragma unroll
        for (int ks = 0; ks < 4; ++ks) {
            const int kb0 = ks * 16;
            uint32_t a[2][4], bf[2][4];
            #pragma unroll
            for (int mt = 0; mt < 2; ++mt)
                ldsm4(a[mt], sa + (mw * 32 + mt * 16 + a_row) * 72 + kb0 + a_kof);
            #pragma unroll
            for (int nt2 = 0; nt2 < 2; ++nt2)
                ldsm4(bf[nt2], sb + (nw * 32 + nt2 * 16 + b_row) * 72 + kb0 + b_kof);
            #pragma unroll
            for (int mt = 0; mt < 2; ++mt)
                #pragma unroll
                for (int nt = 0; nt < 4; ++nt)
                    mma16(acc[mt][nt], a[mt], bf[nt >> 1] + (nt & 1) * 2);
        }
        __syncthreads();                          // close MMA(kc)
        if (kc + 2 < 16) issueWd(kc & 1, kc + 2);
        if (kc + 1 < 16) produce(kc + 1);
    }

    // LN stats reduction: 4 partials per row
    sred[prow * 8 + (tid & 3) * 2]     = psum;
    sred[prow * 8 + (tid & 3) * 2 + 1] = psq;
    __syncthreads();
    if (tid < 64) {
        float s = 0.f, q = 0.f;
        #pragma unroll
        for (int i = 0; i < 4; ++i) {
            s += sred[tid * 8 + i * 2];
            q += sred[tid * 8 + i * 2 + 1];
        }
        const float mu  = s * (1.f / 1024.f);
        const float var = q * (1.f / 1024.f) - mu * mu;
        smu[tid] = mu;
        srs[tid] = rsqrtf(var + 1e-5f);
    }
    __syncthreads();

    // epilogue: hd = relu(rstd*(acc - mu*s1) + s2) -> g_hd
    #pragma unroll
    for (int mt = 0; mt < 2; ++mt) {
        #pragma unroll
        for (int nt = 0; nt < 4; ++nt) {
            const int row = mw * 32 + mt * 16 + gid;
            const int col = nw * 32 + nt * 8 + 2 * tig;
            const float mu0 = smu[row],     rs0 = srs[row];
            const float mu1 = smu[row + 8], rs1 = srs[row + 8];
            const float s10 = ss1[col], s11 = ss1[col + 1];
            const float s20 = ss2[col], s21 = ss2[col + 1];
            const float* c = acc[mt][nt];
            const size_t o = (size_t)(t0 + row) * BN + col;
            __half2 h0 = __floats2half2_rn(
                fmaxf(rs0 * (c[0] - mu0 * s10) + s20, 0.f),
                fmaxf(rs0 * (c[1] - mu0 * s11) + s21, 0.f));
            __half2 h1 = __floats2half2_rn(
                fmaxf(rs1 * (c[2] - mu1 * s10) + s20, 0.f),
                fmaxf(rs1 * (c[3] - mu1 * s11) + s21, 0.f));
            *(uint32_t*)(g_hd + o)          = *(uint32_t*)&h0;
            *(uint32_t*)(g_hd + o + 8 * BN) = *(uint32_t*)&h1;
        }
    }
}

// ------------------------------------------------------------------ kernel 3
// CTA: 128 tokens x 128 out-cols, 512 threads (16 warps 4x4). Grid (8, 256).
// ssc shortcut staged via cp.async (prefetch overlaps MMAs) — proven version.
static constexpr int G2_ST    = 136;                   // halves
static constexpr int G2_HD    = 0;                     // shd 128x136
static constexpr int G2_WU    = 128 * G2_ST;           // swu 128x136
static constexpr int G2_SC    = G2_WU + 128 * G2_ST;   // ssc 128x136
static constexpr int G2_END   = G2_SC + 128 * G2_ST;   // halves
static constexpr int G2_SMEM  = G2_END * 2 + 128 * 4;  // 104960 B

__global__ __launch_bounds__(512, 2) void gemm2(
    const float* __restrict__ bup, float* __restrict__ out)
{
    extern __shared__ __half smC[];
    __half* shd = smC + G2_HD;
    __half* swu = smC + G2_WU;
    __half* ssc = smC + G2_SC;
    float*  sbup = (float*)(smC + G2_END);
    const int tid  = threadIdx.x;
    const int lane = tid & 31, warp = tid >> 5;
    const int nc = blockIdx.x;                 // col chunk (fastest)
    const int t0 = blockIdx.y * 128;           // token tile

    const int mw = warp >> 2, nw = warp & 3;   // 4 x 4
    const int gid = lane >> 2, tig = lane & 3;

    const int a_row = (lane & 7) + ((lane >> 3) & 1) * 8;
    const int a_kof = (lane >> 4) * 8;
    const int b_row = (lane & 7) + (lane >> 4) * 8;
    const int b_kof = ((lane >> 3) & 1) * 8;

    #pragma unroll
    for (int hk = 0; hk < 2; ++hk) {
        const int k0 = hk * 64;
        #pragma unroll
        for (int p = 0; p < 2; ++p) {           // hd: 128 x 64 halves
            const int idx = p * 512 + tid;
            const int row = idx >> 3, j = (idx & 7) * 8;
            cp16(shd + row * G2_ST + k0 + j, g_hd + (size_t)(t0 + row) * BN + k0 + j);
        }
        #pragma unroll
        for (int p = 0; p < 2; ++p) {           // Wu: 128 x 64 halves
            const int idx = p * 512 + tid;
            const int nn = idx >> 3, j = (idx & 7) * 8;
            cp16(swu + nn * G2_ST + k0 + j,
                 g_Wu + (size_t)(nc * 128 + nn) * BN + k0 + j);
        }
        cp_commit();
    }
    #pragma unroll
    for (int p = 0; p < 4; ++p) {               // shortcut: 128 x 128 halves
        const int idx = p * 512 + tid;
        const int row = idx >> 4, j = (idx & 15) * 8;
        cp16(ssc + row * G2_ST + j,
             g_sc + (size_t)(t0 + row) * DDIM + nc * 128 + j);
    }
    if (tid < 32) cp16(sbup + tid * 4, bup + nc * 128 + tid * 4);
    cp_commit();

    float acc[2][4][4];
    #pragma unroll
    for (int i = 0; i < 2; ++i)
        #pragma unroll
        for (int j = 0; j < 4; ++j)
            #pragma unroll
            for (int q = 0; q < 4; ++q) acc[i][j][q] = 0.f;

    #pragma unroll
    for (int hk = 0; hk < 2; ++hk) {
        if (hk == 0) cp_wait<2>(); else cp_wait<1>();
        __syncthreads();
        #pragma unroll
        for (int ks = 0; ks < 4; ++ks) {
            const int kb0 = hk * 64 + ks * 16;
            uint32_t a[2][4], bf[2][4];
            #pragma unroll
            for (int mt = 0; mt < 2; ++mt)
                ldsm4(a[mt], shd + (mw * 32 + mt * 16 + a_row) * G2_ST + kb0 + a_kof);
            #pragma unroll
            for (int nt2 = 0; nt2 < 2; ++nt2)
                ldsm4(bf[nt2], swu + (nw * 32 + nt2 * 16 + b_row) * G2_ST + kb0 + b_kof);
            #pragma unroll
            for (int mt = 0; mt < 2; ++mt)
                #pragma unroll
                for (int nt = 0; nt < 4; ++nt)
                    mma16(acc[mt][nt], a[mt], bf[nt >> 1] + (nt & 1) * 2);
        }
    }

    cp_wait<0>();
    __syncthreads();

    #pragma unroll
    for (int mt = 0; mt < 2; ++mt) {
        #pragma unroll
        for (int nt = 0; nt < 4; ++nt) {
            const int row  = mw * 32 + mt * 16 + gid;
            const int col  = nw * 32 + nt * 8 + 2 * tig;
            const int gcol = nc * 128 + col;
            const float b0 = sbup[col], b1 = sbup[col + 1];
            const size_t off  = (size_t)(t0 + row) * DDIM + gcol;
            const size_t off2 = off + (size_t)8 * DDIM;
            const float* c = acc[mt][nt];
            const float2 s0 = __half22float2(*(const __half2*)(ssc + row * G2_ST + col));
            const float2 s1 = __half22float2(*(const __half2*)(ssc + (row + 8) * G2_ST + col));
            float2 o0, o1;
            o0.x = c[0] + b0 + s0.x; o0.y = c[1] + b1 + s0.y;
            o1.x = c[2] + b0 + s1.x; o1.y = c[3] + b1 + s1.y;
            *(float2*)(out + off)  = o0;
            *(float2*)(out + off2) = o1;
        }
    }
}

// ------------------------------------------------------------------ launch
extern "C" void kernel_launch(void* const* d_in, const int* in_sizes, int n_in,
                              void* d_out, int out_size) {
    const float* x     = (const float*)d_in[0];
    const float* res   = (const float*)d_in[1];
    const float* gamma = (const float*)d_in[2];
    const float* beta  = (const float*)d_in[3];
    const float* Wd    = (const float*)d_in[4];
    const float* bd    = (const float*)d_in[5];
    const float* Wu    = (const float*)d_in[6];
    const float* bup   = (const float*)d_in[7];
    float* out = (float*)d_out;

    static bool attr_done = false;
    if (!attr_done) {
        cudaFuncSetAttribute(gemm1f, cudaFuncAttributeMaxDynamicSharedMemorySize, F_SMEM);
        cudaFuncSetAttribute(gemm2, cudaFuncAttributeMaxDynamicSharedMemorySize, G2_SMEM);
        attr_done = true;
    }

    prep<<<256, 256>>>(Wd, Wu, gamma, beta, bd);
    gemm1f<<<512, 256, F_SMEM>>>(x, res);
    gemm2<<<dim3(8, 256), 512, G2_SMEM>>>(bup, out);
}